// round 2
// baseline (speedup 1.0000x reference)
#include <cuda_runtime.h>
#include <cuda_bf16.h>

// Problem constants
#define B 2
#define HH 64
#define CC 64
#define CQK 8
#define NP 16            // pooled grid per dim
#define NTOK 4096        // NP^3
#define POOL 4

// Attention tiling
#define TQ 64
#define TK 64
#define ATHREADS 256

// log2(e) / sqrt(8)
#define QSCALE (1.4426950408889634f / 2.8284271247461903f)

// ---------------- scratch (device globals; no allocation allowed) ----------------
__device__ float g_xp [B * NTOK * CC];     // pooled x
__device__ float g_qf [B * NTOK * CQK];
__device__ float g_kf [B * NTOK * CQK];
__device__ float g_vf [B * NTOK * CC];
__device__ float g_att[B * NTOK * CC];     // attended (pooled resolution)

__device__ __forceinline__ float fast_ex2(float x) {
    float y;
    asm("ex2.approx.ftz.f32 %0, %1;" : "=f"(y) : "f"(x));
    return y;
}

// ---------------- 1) pool x: [2,64,64,64,64] -> [2,16,16,16,64] ----------------
// 16 tokens per block, 16 float4-lanes per token. Each thread averages 64 voxels
// for its 4 channels via LDG.128.
__global__ __launch_bounds__(256) void pool_kernel(const float* __restrict__ x) {
    const int tid = threadIdx.x;
    const int tok_local = tid >> 4;      // 0..15
    const int c4 = tid & 15;             // float4 group (4 channels)
    const int bt = blockIdx.x * 16 + tok_local;   // 0..8191
    const int b  = bt >> 12;
    const int rem = bt & 4095;
    const int h0 = ((rem >> 8) & 15) << 2;
    const int w0 = ((rem >> 4) & 15) << 2;
    const int d0 = (rem & 15) << 2;

    const float4* __restrict__ xv = (const float4*)x;
    float sx = 0.f, sy = 0.f, sz = 0.f, sw = 0.f;

#pragma unroll
    for (int i = 0; i < 4; i++) {
#pragma unroll
        for (int j = 0; j < 4; j++) {
            // float4 index of (b, h0+i, w0+j, d0, c4*4)
            int base = ((((b * HH + h0 + i) * HH + (w0 + j)) * HH + d0) << 4) + c4;
#pragma unroll
            for (int k = 0; k < 4; k++) {
                float4 t = xv[base + (k << 4)];
                sx += t.x; sy += t.y; sz += t.z; sw += t.w;
            }
        }
    }
    const float inv = 1.0f / 64.0f;
    float4 o = make_float4(sx * inv, sy * inv, sz * inv, sw * inv);
    ((float4*)g_xp)[bt * 16 + c4] = o;
}

// ---------------- 2) project pooled x -> qf, kf, vf ----------------
// 4 tokens per block (256 threads). thread = (token_local, channel).
__global__ __launch_bounds__(256) void proj_kernel(
    const float* __restrict__ Wq, const float* __restrict__ bq,
    const float* __restrict__ Wk, const float* __restrict__ bk,
    const float* __restrict__ Wv, const float* __restrict__ bv) {
    __shared__ float sx[4][CC];
    const int tid = threadIdx.x;
    const int lt = tid >> 6;           // token within block
    const int c  = tid & 63;           // channel
    const int bt = blockIdx.x * 4 + lt;   // global token 0..8191

    sx[lt][c] = g_xp[bt * CC + c];
    __syncthreads();

    // v projection: every thread one output channel
    float av = bv[c];
#pragma unroll
    for (int i = 0; i < CC; i++) av += sx[lt][i] * Wv[i * CC + c];
    g_vf[bt * CC + c] = av;

    if (c < CQK) {
        float aq = bq[c];
#pragma unroll
        for (int i = 0; i < CC; i++) aq += sx[lt][i] * Wq[i * CQK + c];
        g_qf[bt * CQK + c] = aq;
    } else if (c < 2 * CQK) {
        const int ck = c - CQK;
        float ak = bk[ck];
#pragma unroll
        for (int i = 0; i < CC; i++) ak += sx[lt][i] * Wk[i * CQK + ck];
        g_kf[bt * CQK + ck] = ak;
    }
}

// ---------------- 3) flash attention (fp32 SIMT) ----------------
// Grid: 2 batches x 64 query-tiles = 128 CTAs, 256 threads.
// Each thread accumulates a 4x4 block of O (4 queries x 4 channels).
__global__ __launch_bounds__(ATHREADS) void attn_kernel() {
    __shared__ float sQ[TQ][9];        // padded (bank-spread), holds q * QSCALE
    __shared__ float sK[TK][9];        // padded
    __shared__ float sV[TK][CC];
    __shared__ float sS[TQ][TK + 4];   // scores then probabilities
    __shared__ float sM[TQ], sL[TQ], sScale[TQ];

    const int tid = threadIdx.x;
    const int b  = blockIdx.x >> 6;
    const int q0 = (blockIdx.x & 63) * TQ;

    // load + prescale Q
    for (int i = tid; i < TQ * CQK; i += ATHREADS)
        sQ[i >> 3][i & 7] = g_qf[(b * NTOK + q0 + (i >> 3)) * CQK + (i & 7)] * QSCALE;
    if (tid < TQ) { sM[tid] = -1e30f; sL[tid] = 0.f; }

    float acc[4][4];
#pragma unroll
    for (int i = 0; i < 4; i++)
#pragma unroll
        for (int j = 0; j < 4; j++) acc[i][j] = 0.f;

    const int tq = tid >> 4;     // query group (x4)
    const int tc = tid & 15;     // channel group (x4)
    const int rq = tid >> 2;     // row for softmax ops
    const int sub = tid & 3;

    __syncthreads();

    for (int kb = 0; kb < NTOK; kb += TK) {
        // load K tile
        for (int i = tid; i < TK * CQK; i += ATHREADS)
            sK[i >> 3][i & 7] = g_kf[(b * NTOK + kb + (i >> 3)) * CQK + (i & 7)];
        // load V tile (float4)
        {
            const float4* vsrc = (const float4*)&g_vf[(b * NTOK + kb) * CC];
            float4* vdst = (float4*)&sV[0][0];
#pragma unroll
            for (int i = 0; i < (TK * CC / 4) / ATHREADS; i++)
                vdst[tid + ATHREADS * i] = vsrc[tid + ATHREADS * i];
        }
        __syncthreads();

        // S = (Q*QSCALE) . K   (log2-domain scaled scores)
        for (int i = tid; i < TQ * TK; i += ATHREADS) {
            const int q = i >> 6;   // TK == 64
            const int k = i & 63;
            float s = 0.f;
#pragma unroll
            for (int c = 0; c < CQK; c++) s += sQ[q][c] * sK[k][c];
            sS[q][k] = s;
        }
        __syncthreads();

        // row max (4 threads per row, 16 entries each)
        float mloc = -1e30f;
#pragma unroll
        for (int j = 0; j < 16; j++) mloc = fmaxf(mloc, sS[rq][sub * 16 + j]);
        mloc = fmaxf(mloc, __shfl_xor_sync(0xffffffffu, mloc, 1));
        mloc = fmaxf(mloc, __shfl_xor_sync(0xffffffffu, mloc, 2));
        if (sub == 0) {
            const float mo = sM[rq];
            const float mn = fmaxf(mo, mloc);
            sScale[rq] = fast_ex2(mo - mn);
            sM[rq] = mn;
        }
        __syncthreads();

        // p = exp2(s - m), accumulate row sum
        {
            const float m = sM[rq];
            float suml = 0.f;
#pragma unroll
            for (int j = 0; j < 16; j++) {
                const float p = fast_ex2(sS[rq][sub * 16 + j] - m);
                sS[rq][sub * 16 + j] = p;
                suml += p;
            }
            suml += __shfl_xor_sync(0xffffffffu, suml, 1);
            suml += __shfl_xor_sync(0xffffffffu, suml, 2);
            if (sub == 0) sL[rq] = sL[rq] * sScale[rq] + suml;
        }
        __syncthreads();

        // rescale accumulators, then O += P @ V
        {
            float sc[4];
#pragma unroll
            for (int i = 0; i < 4; i++) sc[i] = sScale[4 * tq + i];
#pragma unroll
            for (int i = 0; i < 4; i++)
#pragma unroll
                for (int j = 0; j < 4; j++) acc[i][j] *= sc[i];
        }
#pragma unroll 4
        for (int k = 0; k < TK; k++) {
            const float4 v = *(const float4*)&sV[k][4 * tc];
            const float p0 = sS[4 * tq + 0][k];
            const float p1 = sS[4 * tq + 1][k];
            const float p2 = sS[4 * tq + 2][k];
            const float p3 = sS[4 * tq + 3][k];
            acc[0][0] += p0 * v.x; acc[0][1] += p0 * v.y; acc[0][2] += p0 * v.z; acc[0][3] += p0 * v.w;
            acc[1][0] += p1 * v.x; acc[1][1] += p1 * v.y; acc[1][2] += p1 * v.z; acc[1][3] += p1 * v.w;
            acc[2][0] += p2 * v.x; acc[2][1] += p2 * v.y; acc[2][2] += p2 * v.z; acc[2][3] += p2 * v.w;
            acc[3][0] += p3 * v.x; acc[3][1] += p3 * v.y; acc[3][2] += p3 * v.z; acc[3][3] += p3 * v.w;
        }
        __syncthreads();
    }

    // epilogue: normalize, write attended
#pragma unroll
    for (int i = 0; i < 4; i++) {
        const float inv = 1.0f / sL[4 * tq + i];
        float4 o = make_float4(acc[i][0] * inv, acc[i][1] * inv,
                               acc[i][2] * inv, acc[i][3] * inv);
        *(float4*)&g_att[(b * NTOK + q0 + 4 * tq + i) * CC + 4 * tc] = o;
    }
}

// ---------------- 4) out = x + gamma * upsample(attended) ----------------
__global__ __launch_bounds__(256) void fuse_kernel(const float* __restrict__ x,
                                                   const float* __restrict__ gamma,
                                                   float* __restrict__ out) {
    const int i = blockIdx.x * blockDim.x + threadIdx.x;   // float4 index, 8388608 total
    const float g = __ldg(gamma);

    const int c4 = i & 15;
    const int d  = (i >> 4)  & 63;
    const int w  = (i >> 10) & 63;
    const int h  = (i >> 16) & 63;
    const int b  = i >> 22;
    const int tok = ((b * NP + (h >> 2)) * NP + (w >> 2)) * NP + (d >> 2);

    const float4 a  = ((const float4*)g_att)[tok * 16 + c4];
    const float4 xx = ((const float4*)x)[i];
    float4 o = make_float4(xx.x + g * a.x, xx.y + g * a.y,
                           xx.z + g * a.z, xx.w + g * a.w);
    ((float4*)out)[i] = o;
}

// ---------------- launch ----------------
extern "C" void kernel_launch(void* const* d_in, const int* in_sizes, int n_in,
                              void* d_out, int out_size) {
    const float* x     = (const float*)d_in[0];
    const float* Wq    = (const float*)d_in[1];
    const float* bq    = (const float*)d_in[2];
    const float* Wk    = (const float*)d_in[3];
    const float* bk    = (const float*)d_in[4];
    const float* Wv    = (const float*)d_in[5];
    const float* bv    = (const float*)d_in[6];
    const float* gamma = (const float*)d_in[7];
    float* out = (float*)d_out;

    pool_kernel<<<512, 256>>>(x);                       // 8192 tokens / 16 per block
    proj_kernel<<<2048, 256>>>(Wq, bq, Wk, bk, Wv, bv); // 8192 tokens / 4 per block
    attn_kernel<<<128, ATHREADS>>>();                   // 2 batches x 64 q-tiles
    fuse_kernel<<<33554432 / 4 / 256, 256>>>(x, gamma, out);
}

// round 4
// speedup vs baseline: 2.9408x; 2.9408x over previous
#include <cuda_runtime.h>
#include <cuda_bf16.h>
#include <cstdint>

// Problem constants
#define B 2
#define HH 64
#define CC 64
#define CQK 8
#define NP 16            // pooled grid per dim
#define NTOK 4096        // NP^3
#define POOL 4

// log2(e) / sqrt(8)
#define QSCALE (1.4426950408889634f / 2.8284271247461903f)

// attention tiling
#define TQ 64
#define TK 64
#define KS 24            // smem row stride (bf16 elems) for Q/K (48B, 16B-aligned, LDSM conflict-free)
#define VS 72            // smem row stride for V (144B)

// ---------------- scratch (device globals; no allocation allowed) ----------------
__device__ float          g_xp [B * NTOK * CC];   // pooled x
__device__ __nv_bfloat16  g_q16[B * NTOK * 16];   // q, prescaled, padded k=16
__device__ __nv_bfloat16  g_k16[B * NTOK * 16];   // k, padded k=16
__device__ __nv_bfloat16  g_v16[B * NTOK * CC];   // v
__device__ float          g_att[B * NTOK * CC];   // attended (pooled resolution)

__device__ __forceinline__ float fast_ex2(float x) {
    float y;
    asm("ex2.approx.ftz.f32 %0, %1;" : "=f"(y) : "f"(x));
    return y;
}

__device__ __forceinline__ uint32_t smem_u32(const void* p) {
    return (uint32_t)__cvta_generic_to_shared(p);
}

__device__ __forceinline__ void ldsm_x4(uint32_t& r0, uint32_t& r1, uint32_t& r2, uint32_t& r3,
                                        uint32_t addr) {
    asm volatile("ldmatrix.sync.aligned.m8n8.x4.shared.b16 {%0,%1,%2,%3}, [%4];"
                 : "=r"(r0), "=r"(r1), "=r"(r2), "=r"(r3) : "r"(addr));
}
__device__ __forceinline__ void ldsm_x4_t(uint32_t& r0, uint32_t& r1, uint32_t& r2, uint32_t& r3,
                                          uint32_t addr) {
    asm volatile("ldmatrix.sync.aligned.m8n8.x4.trans.shared.b16 {%0,%1,%2,%3}, [%4];"
                 : "=r"(r0), "=r"(r1), "=r"(r2), "=r"(r3) : "r"(addr));
}
__device__ __forceinline__ void mma_bf16(float* d, const uint32_t* a, uint32_t b0, uint32_t b1) {
    asm volatile("mma.sync.aligned.m16n8k16.row.col.f32.bf16.bf16.f32 "
                 "{%0,%1,%2,%3}, {%4,%5,%6,%7}, {%8,%9}, {%0,%1,%2,%3};"
                 : "+f"(d[0]), "+f"(d[1]), "+f"(d[2]), "+f"(d[3])
                 : "r"(a[0]), "r"(a[1]), "r"(a[2]), "r"(a[3]), "r"(b0), "r"(b1));
}
__device__ __forceinline__ uint32_t pack_bf16x2(float hi, float lo) {
    uint32_t d;
    asm("cvt.rn.bf16x2.f32 %0, %1, %2;" : "=r"(d) : "f"(hi), "f"(lo));
    return d;
}
__device__ __forceinline__ void cp16(uint32_t dst, const void* src) {
    asm volatile("cp.async.cg.shared.global [%0], [%1], 16;" :: "r"(dst), "l"(src));
}
__device__ __forceinline__ void cp_commit() {
    asm volatile("cp.async.commit_group;" ::: "memory");
}
template<int N> __device__ __forceinline__ void cp_wait() {
    asm volatile("cp.async.wait_group %0;" :: "n"(N) : "memory");
}

// ---------------- 1) pool x: [2,64,64,64,64] -> [2,16,16,16,64] ----------------
__global__ __launch_bounds__(256) void pool_kernel(const float* __restrict__ x) {
    const int tid = threadIdx.x;
    const int tok_local = tid >> 4;
    const int c4 = tid & 15;
    const int bt = blockIdx.x * 16 + tok_local;
    const int b  = bt >> 12;
    const int rem = bt & 4095;
    const int h0 = ((rem >> 8) & 15) << 2;
    const int w0 = ((rem >> 4) & 15) << 2;
    const int d0 = (rem & 15) << 2;

    const float4* __restrict__ xv = (const float4*)x;
    float sx = 0.f, sy = 0.f, sz = 0.f, sw = 0.f;
#pragma unroll
    for (int i = 0; i < 4; i++) {
#pragma unroll
        for (int j = 0; j < 4; j++) {
            int base = ((((b * HH + h0 + i) * HH + (w0 + j)) * HH + d0) << 4) + c4;
#pragma unroll
            for (int k = 0; k < 4; k++) {
                float4 t = xv[base + (k << 4)];
                sx += t.x; sy += t.y; sz += t.z; sw += t.w;
            }
        }
    }
    const float inv = 1.0f / 64.0f;
    ((float4*)g_xp)[bt * 16 + c4] = make_float4(sx * inv, sy * inv, sz * inv, sw * inv);
}

// ---------------- 2) project pooled x -> q16, k16, v16 ----------------
__global__ __launch_bounds__(256) void proj_kernel(
    const float* __restrict__ Wq, const float* __restrict__ bq,
    const float* __restrict__ Wk, const float* __restrict__ bk,
    const float* __restrict__ Wv, const float* __restrict__ bv) {
    __shared__ float sx[4][CC];
    const int tid = threadIdx.x;
    const int lt = tid >> 6;
    const int c  = tid & 63;
    const int bt = blockIdx.x * 4 + lt;

    sx[lt][c] = g_xp[bt * CC + c];
    __syncthreads();

    float av = bv[c];
#pragma unroll
    for (int i = 0; i < CC; i++) av += sx[lt][i] * Wv[i * CC + c];
    g_v16[bt * CC + c] = __float2bfloat16(av);

    if (c < CQK) {
        float aq = bq[c];
#pragma unroll
        for (int i = 0; i < CC; i++) aq += sx[lt][i] * Wq[i * CQK + c];
        g_q16[bt * 16 + c] = __float2bfloat16(aq * (float)QSCALE);
        g_q16[bt * 16 + 8 + c] = __float2bfloat16(0.f);
    } else if (c < 2 * CQK) {
        const int ck = c - CQK;
        float ak = bk[ck];
#pragma unroll
        for (int i = 0; i < CC; i++) ak += sx[lt][i] * Wk[i * CQK + ck];
        g_k16[bt * 16 + ck] = __float2bfloat16(ak);
        g_k16[bt * 16 + 8 + ck] = __float2bfloat16(0.f);
    }
}

// ---------------- 3) flash attention, bf16 HMMA ----------------
// Grid: 2 batches x 64 query-tiles = 128 CTAs, 128 threads (4 warps).
// Warp w owns query rows [16w, 16w+16). Per warp: S = Q(16x16) K^T -> 16x64,
// online softmax in registers, O += P(16x64) V(64x64), all via m16n8k16 bf16 mma.
__global__ __launch_bounds__(128) void attn_kernel() {
    __shared__ __align__(16) __nv_bfloat16 sQ[TQ * KS];
    __shared__ __align__(16) __nv_bfloat16 sK[2][TK * KS];
    __shared__ __align__(16) __nv_bfloat16 sV[2][TK * VS];

    const int tid  = threadIdx.x;
    const int warp = tid >> 5;
    const int lane = tid & 31;
    const int b  = blockIdx.x >> 6;
    const int q0 = (blockIdx.x & 63) * TQ;

    const __nv_bfloat16* gk = g_k16 + (size_t)b * NTOK * 16;
    const __nv_bfloat16* gv = g_v16 + (size_t)b * NTOK * CC;

    // load Q tile (64 rows x 16) -> padded smem rows
    {
        const uint4* qsrc = (const uint4*)(g_q16 + (size_t)(b * NTOK + q0) * 16);
        const int row = tid >> 1, seg = tid & 1;
        *(uint4*)&sQ[row * KS + seg * 8] = qsrc[tid];
    }

    // async tile loader
    auto load_tile = [&](int buf, int t) {
        const int kb = t * TK;
        // K: 64 rows x 16 elems = 128 x 16B chunks, 1 per thread
        {
            const int r = tid >> 1, seg = tid & 1;
            cp16(smem_u32(&sK[buf][r * KS + seg * 8]), gk + (kb + r) * 16 + seg * 8);
        }
        // V: 64 rows x 64 elems = 512 x 16B chunks, 4 per thread
#pragma unroll
        for (int j = 0; j < 4; j++) {
            const int cchunk = tid + 128 * j;
            const int r = cchunk >> 3, seg = cchunk & 7;
            cp16(smem_u32(&sV[buf][r * VS + seg * 8]), gv + (kb + r) * CC + seg * 8);
        }
    };

    load_tile(0, 0);
    cp_commit();
    __syncthreads();   // sQ visible

    // Q A-fragment (one ldmatrix.x4, reused every tile)
    uint32_t qa[4];
    ldsm_x4(qa[0], qa[1], qa[2], qa[3],
            smem_u32(&sQ[(16 * warp + (lane & 15)) * KS + (lane >> 4) * 8]));

    float m0 = -1e30f, m1 = -1e30f;     // row maxima (log2 domain)
    float l0 = 0.f, l1 = 0.f;           // per-thread partial row sums
    float o[8][4];
#pragma unroll
    for (int ni = 0; ni < 8; ni++)
#pragma unroll
        for (int j = 0; j < 4; j++) o[ni][j] = 0.f;

    for (int t = 0; t < NTOK / TK; t++) {
        if (t + 1 < NTOK / TK) { load_tile((t + 1) & 1, t + 1); cp_commit(); cp_wait<1>(); }
        else                   { cp_wait<0>(); }
        __syncthreads();
        const int buf = t & 1;

        // ---- S = Q K^T : 8 n-tiles of 16x8 ----
        float s[8][4];
#pragma unroll
        for (int p = 0; p < 4; p++) {
            uint32_t r0, r1, r2, r3;
            ldsm_x4(r0, r1, r2, r3,
                    smem_u32(&sK[buf][(16 * p + (lane & 15)) * KS + (lane >> 4) * 8]));
            s[2 * p][0] = s[2 * p][1] = s[2 * p][2] = s[2 * p][3] = 0.f;
            s[2 * p + 1][0] = s[2 * p + 1][1] = s[2 * p + 1][2] = s[2 * p + 1][3] = 0.f;
            mma_bf16(s[2 * p],     qa, r0, r2);
            mma_bf16(s[2 * p + 1], qa, r1, r3);
        }

        // ---- online softmax (scores already in log2 domain) ----
        float mx0 = -1e30f, mx1 = -1e30f;
#pragma unroll
        for (int ni = 0; ni < 8; ni++) {
            mx0 = fmaxf(mx0, fmaxf(s[ni][0], s[ni][1]));
            mx1 = fmaxf(mx1, fmaxf(s[ni][2], s[ni][3]));
        }
        mx0 = fmaxf(mx0, __shfl_xor_sync(0xffffffffu, mx0, 1));
        mx0 = fmaxf(mx0, __shfl_xor_sync(0xffffffffu, mx0, 2));
        mx1 = fmaxf(mx1, __shfl_xor_sync(0xffffffffu, mx1, 1));
        mx1 = fmaxf(mx1, __shfl_xor_sync(0xffffffffu, mx1, 2));

        const float mn0 = fmaxf(m0, mx0);
        const float mn1 = fmaxf(m1, mx1);
        const float al0 = fast_ex2(m0 - mn0);
        const float al1 = fast_ex2(m1 - mn1);
        m0 = mn0; m1 = mn1;

        float ps0 = 0.f, ps1 = 0.f;
#pragma unroll
        for (int ni = 0; ni < 8; ni++) {
            s[ni][0] = fast_ex2(s[ni][0] - mn0);
            s[ni][1] = fast_ex2(s[ni][1] - mn0);
            s[ni][2] = fast_ex2(s[ni][2] - mn1);
            s[ni][3] = fast_ex2(s[ni][3] - mn1);
            ps0 += s[ni][0] + s[ni][1];
            ps1 += s[ni][2] + s[ni][3];
        }
        l0 = l0 * al0 + ps0;
        l1 = l1 * al1 + ps1;
#pragma unroll
        for (int ni = 0; ni < 8; ni++) {
            o[ni][0] *= al0; o[ni][1] *= al0;
            o[ni][2] *= al1; o[ni][3] *= al1;
        }

        // ---- P -> bf16 A-fragments (reuse C-frag layout) ----
        uint32_t pa[4][4];
#pragma unroll
        for (int kc = 0; kc < 4; kc++) {
            pa[kc][0] = pack_bf16x2(s[2 * kc][1],     s[2 * kc][0]);
            pa[kc][1] = pack_bf16x2(s[2 * kc][3],     s[2 * kc][2]);
            pa[kc][2] = pack_bf16x2(s[2 * kc + 1][1], s[2 * kc + 1][0]);
            pa[kc][3] = pack_bf16x2(s[2 * kc + 1][3], s[2 * kc + 1][2]);
        }

        // ---- O += P V ----
#pragma unroll
        for (int kc = 0; kc < 4; kc++) {
#pragma unroll
            for (int np = 0; np < 4; np++) {
                uint32_t r0, r1, r2, r3;
                ldsm_x4_t(r0, r1, r2, r3,
                          smem_u32(&sV[buf][(16 * kc + (lane & 15)) * VS
                                            + np * 16 + (lane >> 4) * 8]));
                mma_bf16(o[2 * np],     pa[kc], r0, r1);
                mma_bf16(o[2 * np + 1], pa[kc], r2, r3);
            }
        }
        __syncthreads();
    }

    // ---- epilogue ----
    l0 += __shfl_xor_sync(0xffffffffu, l0, 1);
    l0 += __shfl_xor_sync(0xffffffffu, l0, 2);
    l1 += __shfl_xor_sync(0xffffffffu, l1, 1);
    l1 += __shfl_xor_sync(0xffffffffu, l1, 2);
    const float inv0 = 1.0f / l0;
    const float inv1 = 1.0f / l1;

    const int row0 = q0 + 16 * warp + (lane >> 2);
    const int row1 = row0 + 8;
    float* out0 = g_att + ((size_t)b * NTOK + row0) * CC;
    float* out1 = g_att + ((size_t)b * NTOK + row1) * CC;
#pragma unroll
    for (int ni = 0; ni < 8; ni++) {
        const int col = 8 * ni + 2 * (lane & 3);
        *(float2*)&out0[col] = make_float2(o[ni][0] * inv0, o[ni][1] * inv0);
        *(float2*)&out1[col] = make_float2(o[ni][2] * inv1, o[ni][3] * inv1);
    }
}

// ---------------- 4) out = x + gamma * upsample(attended) ----------------
__global__ __launch_bounds__(256) void fuse_kernel(const float* __restrict__ x,
                                                   const float* __restrict__ gamma,
                                                   float* __restrict__ out) {
    const int i = blockIdx.x * blockDim.x + threadIdx.x;   // float4 index
    const float g = __ldg(gamma);

    const int c4 = i & 15;
    const int d  = (i >> 4)  & 63;
    const int w  = (i >> 10) & 63;
    const int h  = (i >> 16) & 63;
    const int b  = i >> 22;
    const int tok = ((b * NP + (h >> 2)) * NP + (w >> 2)) * NP + (d >> 2);

    const float4 a  = ((const float4*)g_att)[tok * 16 + c4];
    const float4 xx = ((const float4*)x)[i];
    ((float4*)out)[i] = make_float4(xx.x + g * a.x, xx.y + g * a.y,
                                    xx.z + g * a.z, xx.w + g * a.w);
}

// ---------------- launch ----------------
extern "C" void kernel_launch(void* const* d_in, const int* in_sizes, int n_in,
                              void* d_out, int out_size) {
    const float* x     = (const float*)d_in[0];
    const float* Wq    = (const float*)d_in[1];
    const float* bq    = (const float*)d_in[2];
    const float* Wk    = (const float*)d_in[3];
    const float* bk    = (const float*)d_in[4];
    const float* Wv    = (const float*)d_in[5];
    const float* bv    = (const float*)d_in[6];
    const float* gamma = (const float*)d_in[7];
    float* out = (float*)d_out;

    pool_kernel<<<512, 256>>>(x);
    proj_kernel<<<2048, 256>>>(Wq, bq, Wk, bk, Wv, bv);
    attn_kernel<<<128, 128>>>();
    fuse_kernel<<<33554432 / 4 / 256, 256>>>(x, gamma, out);
}

// round 6
// speedup vs baseline: 7.8178x; 2.6584x over previous
#include <cuda_runtime.h>
#include <cuda_bf16.h>
#include <cstdint>

// Problem constants
#define B 2
#define HH 64
#define CC 64
#define CQK 8
#define NP 16            // pooled grid per dim
#define NTOK 4096        // NP^3
#define POOL 4

// log2(e) / sqrt(8)
#define QSCALE (1.4426950408889634f / 2.8284271247461903f)

// attention tiling
#define TQ 64
#define TK 64
#define KS 24            // smem row stride (bf16) for Q/K
#define VS 72            // smem row stride for V
#define NSPLIT 4
#define TILES_PER_SPLIT (NTOK / TK / NSPLIT)   // 16

// ---------------- scratch (device globals; no allocation allowed) ----------------
__device__ __nv_bfloat16  g_q16[B * NTOK * 16];          // q, prescaled, padded k=16
__device__ __nv_bfloat16  g_k16[B * NTOK * 16];          // k, padded k=16
__device__ __nv_bfloat16  g_v16[B * NTOK * CC];          // v
__device__ float          g_po [NSPLIT * B * NTOK * CC]; // partial O (unnormalized)
__device__ float          g_pm [NSPLIT * B * NTOK];      // partial row max (log2 dom)
__device__ float          g_pl [NSPLIT * B * NTOK];      // partial row sum
__device__ float          g_att[B * NTOK * CC];          // attended (pooled res)

__device__ __forceinline__ float fast_ex2(float x) {
    float y;
    asm("ex2.approx.ftz.f32 %0, %1;" : "=f"(y) : "f"(x));
    return y;
}
__device__ __forceinline__ uint32_t smem_u32(const void* p) {
    return (uint32_t)__cvta_generic_to_shared(p);
}
__device__ __forceinline__ void ldsm_x4(uint32_t& r0, uint32_t& r1, uint32_t& r2, uint32_t& r3,
                                        uint32_t addr) {
    asm volatile("ldmatrix.sync.aligned.m8n8.x4.shared.b16 {%0,%1,%2,%3}, [%4];"
                 : "=r"(r0), "=r"(r1), "=r"(r2), "=r"(r3) : "r"(addr));
}
__device__ __forceinline__ void ldsm_x4_t(uint32_t& r0, uint32_t& r1, uint32_t& r2, uint32_t& r3,
                                          uint32_t addr) {
    asm volatile("ldmatrix.sync.aligned.m8n8.x4.trans.shared.b16 {%0,%1,%2,%3}, [%4];"
                 : "=r"(r0), "=r"(r1), "=r"(r2), "=r"(r3) : "r"(addr));
}
__device__ __forceinline__ void mma_bf16(float* d, const uint32_t* a, uint32_t b0, uint32_t b1) {
    asm volatile("mma.sync.aligned.m16n8k16.row.col.f32.bf16.bf16.f32 "
                 "{%0,%1,%2,%3}, {%4,%5,%6,%7}, {%8,%9}, {%0,%1,%2,%3};"
                 : "+f"(d[0]), "+f"(d[1]), "+f"(d[2]), "+f"(d[3])
                 : "r"(a[0]), "r"(a[1]), "r"(a[2]), "r"(a[3]), "r"(b0), "r"(b1));
}
__device__ __forceinline__ uint32_t pack_bf16x2(float hi, float lo) {
    uint32_t d;
    asm("cvt.rn.bf16x2.f32 %0, %1, %2;" : "=r"(d) : "f"(hi), "f"(lo));
    return d;
}
__device__ __forceinline__ void cp16(uint32_t dst, const void* src) {
    asm volatile("cp.async.cg.shared.global [%0], [%1], 16;" :: "r"(dst), "l"(src));
}
__device__ __forceinline__ void cp_commit() {
    asm volatile("cp.async.commit_group;" ::: "memory");
}
template<int N> __device__ __forceinline__ void cp_wait() {
    asm volatile("cp.async.wait_group %0;" :: "n"(N) : "memory");
}

// ---------------- 1) pool x + project -> q16/k16/v16 (fused) ----------------
// 512 blocks x 256 threads; block handles 16 tokens. Pool into smem, then each
// thread computes projection outputs over 4 token-passes.
__global__ __launch_bounds__(256) void pool_proj_kernel(
    const float* __restrict__ x,
    const float* __restrict__ Wq, const float* __restrict__ bq,
    const float* __restrict__ Wk, const float* __restrict__ bk,
    const float* __restrict__ Wv, const float* __restrict__ bv,
    const float* __restrict__ gamma) {
    if (__ldg(gamma) == 0.0f) return;   // zero-gate: attention contributes nothing

    __shared__ float sx[16][68];        // pooled tokens (padded stride)

    const int tid = threadIdx.x;
    // ---- pooling ----
    {
        const int tok_local = tid >> 4;
        const int c4 = tid & 15;
        const int bt = blockIdx.x * 16 + tok_local;
        const int b  = bt >> 12;
        const int rem = bt & 4095;
        const int h0 = ((rem >> 8) & 15) << 2;
        const int w0 = ((rem >> 4) & 15) << 2;
        const int d0 = (rem & 15) << 2;

        const float4* __restrict__ xv = (const float4*)x;
        float sxx = 0.f, sy = 0.f, sz = 0.f, sw = 0.f;
#pragma unroll
        for (int i = 0; i < 4; i++) {
#pragma unroll
            for (int j = 0; j < 4; j++) {
                int base = ((((b * HH + h0 + i) * HH + (w0 + j)) * HH + d0) << 4) + c4;
#pragma unroll
                for (int k = 0; k < 4; k++) {
                    float4 t = xv[base + (k << 4)];
                    sxx += t.x; sy += t.y; sz += t.z; sw += t.w;
                }
            }
        }
        const float inv = 1.0f / 64.0f;
        sx[tok_local][c4 * 4 + 0] = sxx * inv;
        sx[tok_local][c4 * 4 + 1] = sy * inv;
        sx[tok_local][c4 * 4 + 2] = sz * inv;
        sx[tok_local][c4 * 4 + 3] = sw * inv;
    }
    __syncthreads();

    // ---- projection: 4 passes of 4 tokens ----
    const int c = tid & 63;
    const int lt_base = tid >> 6;       // 0..3
#pragma unroll
    for (int p = 0; p < 4; p++) {
        const int lt = p * 4 + lt_base;
        const int bt = blockIdx.x * 16 + lt;

        float av = bv[c];
#pragma unroll
        for (int i = 0; i < CC; i++) av += sx[lt][i] * Wv[i * CC + c];
        g_v16[bt * CC + c] = __float2bfloat16(av);

        if (c < CQK) {
            float aq = bq[c];
#pragma unroll
            for (int i = 0; i < CC; i++) aq += sx[lt][i] * Wq[i * CQK + c];
            g_q16[bt * 16 + c] = __float2bfloat16(aq * (float)QSCALE);
            g_q16[bt * 16 + 8 + c] = __float2bfloat16(0.f);
        } else if (c < 2 * CQK) {
            const int ck = c - CQK;
            float ak = bk[ck];
#pragma unroll
            for (int i = 0; i < CC; i++) ak += sx[lt][i] * Wk[i * CQK + ck];
            g_k16[bt * 16 + ck] = __float2bfloat16(ak);
            g_k16[bt * 16 + 8 + ck] = __float2bfloat16(0.f);
        }
    }
}

// ---------------- 2) flash attention, bf16 HMMA, split-KV x4 ----------------
// Grid: B x 64 q-tiles x NSPLIT = 512 CTAs, 128 threads (4 warps).
__global__ __launch_bounds__(128) void attn_kernel(const float* __restrict__ gamma) {
    if (__ldg(gamma) == 0.0f) return;

    __shared__ __align__(16) __nv_bfloat16 sQ[TQ * KS];
    __shared__ __align__(16) __nv_bfloat16 sK[2][TK * KS];
    __shared__ __align__(16) __nv_bfloat16 sV[2][TK * VS];

    const int tid  = threadIdx.x;
    const int warp = tid >> 5;
    const int lane = tid & 31;
    const int split = blockIdx.x & (NSPLIT - 1);
    const int qi = (blockIdx.x >> 2) & 63;
    const int b  = blockIdx.x >> 8;
    const int q0 = qi * TQ;
    const int t_begin = split * TILES_PER_SPLIT;
    const int t_end   = t_begin + TILES_PER_SPLIT;

    const __nv_bfloat16* gk = g_k16 + (size_t)b * NTOK * 16;
    const __nv_bfloat16* gv = g_v16 + (size_t)b * NTOK * CC;

    // load Q tile (64 rows x 16)
    {
        const uint4* qsrc = (const uint4*)(g_q16 + (size_t)(b * NTOK + q0) * 16);
        const int row = tid >> 1, seg = tid & 1;
        *(uint4*)&sQ[row * KS + seg * 8] = qsrc[tid];
    }

    auto load_tile = [&](int buf, int t) {
        const int kb = t * TK;
        {
            const int r = tid >> 1, seg = tid & 1;
            cp16(smem_u32(&sK[buf][r * KS + seg * 8]), gk + (kb + r) * 16 + seg * 8);
        }
#pragma unroll
        for (int j = 0; j < 4; j++) {
            const int cchunk = tid + 128 * j;
            const int r = cchunk >> 3, seg = cchunk & 7;
            cp16(smem_u32(&sV[buf][r * VS + seg * 8]), gv + (kb + r) * CC + seg * 8);
        }
    };

    load_tile(0, t_begin);
    cp_commit();
    __syncthreads();   // sQ visible

    uint32_t qa[4];
    ldsm_x4(qa[0], qa[1], qa[2], qa[3],
            smem_u32(&sQ[(16 * warp + (lane & 15)) * KS + (lane >> 4) * 8]));

    float m0 = -1e30f, m1 = -1e30f;
    float l0 = 0.f, l1 = 0.f;
    float o[8][4];
#pragma unroll
    for (int ni = 0; ni < 8; ni++)
#pragma unroll
        for (int j = 0; j < 4; j++) o[ni][j] = 0.f;

    for (int t = t_begin; t < t_end; t++) {
        if (t + 1 < t_end) { load_tile((t + 1 - t_begin) & 1, t + 1); cp_commit(); cp_wait<1>(); }
        else               { cp_wait<0>(); }
        __syncthreads();
        const int buf = (t - t_begin) & 1;

        // ---- S = Q K^T ----
        float s[8][4];
#pragma unroll
        for (int p = 0; p < 4; p++) {
            uint32_t r0, r1, r2, r3;
            ldsm_x4(r0, r1, r2, r3,
                    smem_u32(&sK[buf][(16 * p + (lane & 15)) * KS + (lane >> 4) * 8]));
            s[2 * p][0] = s[2 * p][1] = s[2 * p][2] = s[2 * p][3] = 0.f;
            s[2 * p + 1][0] = s[2 * p + 1][1] = s[2 * p + 1][2] = s[2 * p + 1][3] = 0.f;
            mma_bf16(s[2 * p],     qa, r0, r2);
            mma_bf16(s[2 * p + 1], qa, r1, r3);
        }

        // ---- online softmax (log2 domain) ----
        float mx0 = -1e30f, mx1 = -1e30f;
#pragma unroll
        for (int ni = 0; ni < 8; ni++) {
            mx0 = fmaxf(mx0, fmaxf(s[ni][0], s[ni][1]));
            mx1 = fmaxf(mx1, fmaxf(s[ni][2], s[ni][3]));
        }
        mx0 = fmaxf(mx0, __shfl_xor_sync(0xffffffffu, mx0, 1));
        mx0 = fmaxf(mx0, __shfl_xor_sync(0xffffffffu, mx0, 2));
        mx1 = fmaxf(mx1, __shfl_xor_sync(0xffffffffu, mx1, 1));
        mx1 = fmaxf(mx1, __shfl_xor_sync(0xffffffffu, mx1, 2));

        const float mn0 = fmaxf(m0, mx0);
        const float mn1 = fmaxf(m1, mx1);
        const float al0 = fast_ex2(m0 - mn0);
        const float al1 = fast_ex2(m1 - mn1);
        m0 = mn0; m1 = mn1;

        float ps0 = 0.f, ps1 = 0.f;
#pragma unroll
        for (int ni = 0; ni < 8; ni++) {
            s[ni][0] = fast_ex2(s[ni][0] - mn0);
            s[ni][1] = fast_ex2(s[ni][1] - mn0);
            s[ni][2] = fast_ex2(s[ni][2] - mn1);
            s[ni][3] = fast_ex2(s[ni][3] - mn1);
            ps0 += s[ni][0] + s[ni][1];
            ps1 += s[ni][2] + s[ni][3];
        }
        l0 = l0 * al0 + ps0;
        l1 = l1 * al1 + ps1;
#pragma unroll
        for (int ni = 0; ni < 8; ni++) {
            o[ni][0] *= al0; o[ni][1] *= al0;
            o[ni][2] *= al1; o[ni][3] *= al1;
        }

        // ---- P -> bf16 A-fragments ----
        uint32_t pa[4][4];
#pragma unroll
        for (int kc = 0; kc < 4; kc++) {
            pa[kc][0] = pack_bf16x2(s[2 * kc][1],     s[2 * kc][0]);
            pa[kc][1] = pack_bf16x2(s[2 * kc][3],     s[2 * kc][2]);
            pa[kc][2] = pack_bf16x2(s[2 * kc + 1][1], s[2 * kc + 1][0]);
            pa[kc][3] = pack_bf16x2(s[2 * kc + 1][3], s[2 * kc + 1][2]);
        }

        // ---- O += P V ----
#pragma unroll
        for (int kc = 0; kc < 4; kc++) {
#pragma unroll
            for (int np = 0; np < 4; np++) {
                uint32_t r0, r1, r2, r3;
                ldsm_x4_t(r0, r1, r2, r3,
                          smem_u32(&sV[buf][(16 * kc + (lane & 15)) * VS
                                            + np * 16 + (lane >> 4) * 8]));
                mma_bf16(o[2 * np],     pa[kc], r0, r1);
                mma_bf16(o[2 * np + 1], pa[kc], r2, r3);
            }
        }
        __syncthreads();
    }

    // ---- epilogue: write unnormalized partials + (m, l) ----
    l0 += __shfl_xor_sync(0xffffffffu, l0, 1);
    l0 += __shfl_xor_sync(0xffffffffu, l0, 2);
    l1 += __shfl_xor_sync(0xffffffffu, l1, 1);
    l1 += __shfl_xor_sync(0xffffffffu, l1, 2);

    const int row0 = q0 + 16 * warp + (lane >> 2);
    const int row1 = row0 + 8;
    const size_t pbase = ((size_t)split * B + b) * NTOK;
    float* out0 = g_po + (pbase + row0) * CC;
    float* out1 = g_po + (pbase + row1) * CC;
#pragma unroll
    for (int ni = 0; ni < 8; ni++) {
        const int col = 8 * ni + 2 * (lane & 3);
        *(float2*)&out0[col] = make_float2(o[ni][0], o[ni][1]);
        *(float2*)&out1[col] = make_float2(o[ni][2], o[ni][3]);
    }
    if ((lane & 3) == 0) {
        g_pm[pbase + row0] = m0;  g_pl[pbase + row0] = l0;
        g_pm[pbase + row1] = m1;  g_pl[pbase + row1] = l1;
    }
}

// ---------------- 3) combine split partials -> g_att ----------------
// 2048 blocks x 256 threads; block handles 4 rows x 64 channels.
__global__ __launch_bounds__(256) void combine_kernel(const float* __restrict__ gamma) {
    if (__ldg(gamma) == 0.0f) return;

    const int tid = threadIdx.x;
    const int R = blockIdx.x * 4 + (tid >> 6);   // global row 0..8191
    const int c = tid & 63;
    const int b = R >> 12;
    const int q = R & 4095;

    float m[NSPLIT], l[NSPLIT];
    float M = -1e30f;
#pragma unroll
    for (int s = 0; s < NSPLIT; s++) {
        const size_t idx = ((size_t)s * B + b) * NTOK + q;
        m[s] = g_pm[idx];
        l[s] = g_pl[idx];
        M = fmaxf(M, m[s]);
    }
    float L = 0.f, o = 0.f;
#pragma unroll
    for (int s = 0; s < NSPLIT; s++) {
        const float w = fast_ex2(m[s] - M);
        L += w * l[s];
        o += w * g_po[(((size_t)s * B + b) * NTOK + q) * CC + c];
    }
    g_att[((size_t)b * NTOK + q) * CC + c] = o / L;
}

// ---------------- 4) out = x + gamma * upsample(attended) ----------------
// ILP-2; pure streaming copy fast path when gamma == 0.
__global__ __launch_bounds__(256) void fuse_kernel(const float* __restrict__ x,
                                                   const float* __restrict__ gamma,
                                                   float* __restrict__ out) {
    const float g = __ldg(gamma);
    const int i0 = blockIdx.x * 512 + threadIdx.x;   // float4 index
    const float4* __restrict__ xv = (const float4*)x;
    float4* __restrict__ ov = (float4*)out;

    if (g == 0.0f) {
#pragma unroll
        for (int u = 0; u < 2; u++) {
            const int i = i0 + 256 * u;
            const float4 xx = __ldcs(&xv[i]);
            __stcs(&ov[i], xx);
        }
        return;
    }

#pragma unroll
    for (int u = 0; u < 2; u++) {
        const int i = i0 + 256 * u;
        const int c4 = i & 15;
        const int d  = (i >> 4)  & 63;
        const int w  = (i >> 10) & 63;
        const int h  = (i >> 16) & 63;
        const int b  = i >> 22;
        const int tok = ((b * NP + (h >> 2)) * NP + (w >> 2)) * NP + (d >> 2);

        const float4 a  = ((const float4*)g_att)[tok * 16 + c4];
        const float4 xx = __ldcs(&xv[i]);
        __stcs(&ov[i], make_float4(xx.x + g * a.x, xx.y + g * a.y,
                                   xx.z + g * a.z, xx.w + g * a.w));
    }
}

// ---------------- launch ----------------
extern "C" void kernel_launch(void* const* d_in, const int* in_sizes, int n_in,
                              void* d_out, int out_size) {
    const float* x     = (const float*)d_in[0];
    const float* Wq    = (const float*)d_in[1];
    const float* bq    = (const float*)d_in[2];
    const float* Wk    = (const float*)d_in[3];
    const float* bk    = (const float*)d_in[4];
    const float* Wv    = (const float*)d_in[5];
    const float* bv    = (const float*)d_in[6];
    const float* gamma = (const float*)d_in[7];
    float* out = (float*)d_out;

    pool_proj_kernel<<<512, 256>>>(x, Wq, bq, Wk, bk, Wv, bv, gamma);
    attn_kernel<<<B * 64 * NSPLIT, 128>>>(gamma);
    combine_kernel<<<2048, 256>>>(gamma);
    fuse_kernel<<<8388608 / 512, 256>>>(x, gamma, out);
}

// round 9
// speedup vs baseline: 8.1180x; 1.0384x over previous
#include <cuda_runtime.h>
#include <cuda_bf16.h>
#include <cstdint>

// Problem constants
#define B 2
#define HH 64
#define CC 64
#define CQK 8
#define NP 16            // pooled grid per dim
#define NTOK 4096        // NP^3
#define POOL 4

// log2(e) / sqrt(8)
#define QSCALE (1.4426950408889634f / 2.8284271247461903f)

// attention tiling
#define TQ 64
#define TK 64
#define KS 24            // smem row stride (bf16) for Q/K
#define VS 72            // smem row stride for V
#define NSPLIT 4
#define TILES_PER_SPLIT (NTOK / TK / NSPLIT)   // 16
#define NUNITS (B * 64 * NSPLIT)               // 512 attention work units

#define GRID_P 148       // persistent kernel grid: one CTA per SM, all resident

// Total output: 2*64*64*64*64 floats = 33554432 = 8388608 float4.
#define TOTAL_F4 8388608

// ---------------- scratch (device globals; no allocation allowed) ----------------
__device__ __nv_bfloat16  g_q16[B * NTOK * 16];          // q, prescaled, padded k=16
__device__ __nv_bfloat16  g_k16[B * NTOK * 16];          // k, padded k=16
__device__ __nv_bfloat16  g_v16[B * NTOK * CC];          // v
__device__ float          g_po [NSPLIT * B * NTOK * CC]; // partial O (unnormalized)
__device__ float          g_pm [NSPLIT * B * NTOK];      // partial row max (log2 dom)
__device__ float          g_pl [NSPLIT * B * NTOK];      // partial row sum
__device__ float          g_att[B * NTOK * CC];          // attended (pooled res)

// grid barrier state (self-resetting: count returns to 0, epoch is monotonic)
__device__ int g_bar_count[2];
__device__ int g_bar_epoch[2];

__device__ __forceinline__ float fast_ex2(float x) {
    float y;
    asm("ex2.approx.ftz.f32 %0, %1;" : "=f"(y) : "f"(x));
    return y;
}
__device__ __forceinline__ uint32_t smem_u32(const void* p) {
    return (uint32_t)__cvta_generic_to_shared(p);
}
__device__ __forceinline__ void ldsm_x4(uint32_t& r0, uint32_t& r1, uint32_t& r2, uint32_t& r3,
                                        uint32_t addr) {
    asm volatile("ldmatrix.sync.aligned.m8n8.x4.shared.b16 {%0,%1,%2,%3}, [%4];"
                 : "=r"(r0), "=r"(r1), "=r"(r2), "=r"(r3) : "r"(addr));
}
__device__ __forceinline__ void ldsm_x4_t(uint32_t& r0, uint32_t& r1, uint32_t& r2, uint32_t& r3,
                                          uint32_t addr) {
    asm volatile("ldmatrix.sync.aligned.m8n8.x4.trans.shared.b16 {%0,%1,%2,%3}, [%4];"
                 : "=r"(r0), "=r"(r1), "=r"(r2), "=r"(r3) : "r"(addr));
}
__device__ __forceinline__ void mma_bf16(float* d, const uint32_t* a, uint32_t b0, uint32_t b1) {
    asm volatile("mma.sync.aligned.m16n8k16.row.col.f32.bf16.bf16.f32 "
                 "{%0,%1,%2,%3}, {%4,%5,%6,%7}, {%8,%9}, {%0,%1,%2,%3};"
                 : "+f"(d[0]), "+f"(d[1]), "+f"(d[2]), "+f"(d[3])
                 : "r"(a[0]), "r"(a[1]), "r"(a[2]), "r"(a[3]), "r"(b0), "r"(b1));
}
__device__ __forceinline__ uint32_t pack_bf16x2(float hi, float lo) {
    uint32_t d;
    asm("cvt.rn.bf16x2.f32 %0, %1, %2;" : "=r"(d) : "f"(hi), "f"(lo));
    return d;
}
__device__ __forceinline__ void group_bar(int gidx) {
    asm volatile("bar.sync %0, 128;" :: "r"(gidx + 1) : "memory");
}

// grid-wide barrier: valid because grid == GRID_P <= #SMs and occupancy >= 1,
// so every CTA is resident. Epoch is read BEFORE arrival; monotonic epochs make
// this safe across repeated graph replays.
__device__ __forceinline__ void grid_bar(int i) {
    __syncthreads();
    if (threadIdx.x == 0) {
        const int e = atomicAdd(&g_bar_epoch[i], 0);
        __threadfence();
        if (atomicAdd(&g_bar_count[i], 1) == (int)gridDim.x - 1) {
            g_bar_count[i] = 0;
            __threadfence();
            atomicAdd(&g_bar_epoch[i], 1);
        } else {
            while (atomicAdd(&g_bar_epoch[i], 0) == e) { }
            __threadfence();
        }
    }
    __syncthreads();
}

// ---------------- phase B smem layout ----------------
struct AttnSmem {
    __nv_bfloat16 Q[TQ * KS];
    __nv_bfloat16 K[TK * KS];
    __nv_bfloat16 V[TK * VS];
};

// ---------------- persistent prep kernel: pool+proj | attn | combine ----------------
__global__ __launch_bounds__(256) void prep_kernel(
    const float* __restrict__ x,
    const float* __restrict__ Wq, const float* __restrict__ bq,
    const float* __restrict__ Wk, const float* __restrict__ bk,
    const float* __restrict__ Wv, const float* __restrict__ bv,
    const float* __restrict__ gamma) {
    if (__ldg(gamma) == 0.0f) return;   // zero-gate: attention contributes nothing

    __shared__ __align__(16) union SmemU {
        float sx[16][68];          // phase A: pooled tokens (padded stride)
        AttnSmem grp[2];           // phase B: two 128-thread attention groups
    } smem;

    const int tid = threadIdx.x;

    // ================= Phase A: pool + project, 512 chunks of 16 tokens =================
    for (int chunk = blockIdx.x; chunk < 512; chunk += GRID_P) {
        __syncthreads();   // protect smem reuse across iterations / phases
        {
            const int tok_local = tid >> 4;
            const int c4 = tid & 15;
            const int bt = chunk * 16 + tok_local;
            const int b  = bt >> 12;
            const int rem = bt & 4095;
            const int h0 = ((rem >> 8) & 15) << 2;
            const int w0 = ((rem >> 4) & 15) << 2;
            const int d0 = (rem & 15) << 2;

            const float4* __restrict__ xv = (const float4*)x;
            float sxx = 0.f, sy = 0.f, sz = 0.f, sw = 0.f;
#pragma unroll
            for (int i = 0; i < 4; i++) {
#pragma unroll
                for (int j = 0; j < 4; j++) {
                    int base = ((((b * HH + h0 + i) * HH + (w0 + j)) * HH + d0) << 4) + c4;
#pragma unroll
                    for (int k = 0; k < 4; k++) {
                        float4 t = xv[base + (k << 4)];
                        sxx += t.x; sy += t.y; sz += t.z; sw += t.w;
                    }
                }
            }
            const float inv = 1.0f / 64.0f;
            smem.sx[tok_local][c4 * 4 + 0] = sxx * inv;
            smem.sx[tok_local][c4 * 4 + 1] = sy * inv;
            smem.sx[tok_local][c4 * 4 + 2] = sz * inv;
            smem.sx[tok_local][c4 * 4 + 3] = sw * inv;
        }
        __syncthreads();

        const int c = tid & 63;
        const int lt_base = tid >> 6;
#pragma unroll
        for (int p = 0; p < 4; p++) {
            const int lt = p * 4 + lt_base;
            const int bt = chunk * 16 + lt;

            float av = bv[c];
#pragma unroll
            for (int i = 0; i < CC; i++) av += smem.sx[lt][i] * Wv[i * CC + c];
            g_v16[bt * CC + c] = __float2bfloat16(av);

            if (c < CQK) {
                float aq = bq[c];
#pragma unroll
                for (int i = 0; i < CC; i++) aq += smem.sx[lt][i] * Wq[i * CQK + c];
                g_q16[bt * 16 + c] = __float2bfloat16(aq * (float)QSCALE);
                g_q16[bt * 16 + 8 + c] = __float2bfloat16(0.f);
            } else if (c < 2 * CQK) {
                const int ck = c - CQK;
                float ak = bk[ck];
#pragma unroll
                for (int i = 0; i < CC; i++) ak += smem.sx[lt][i] * Wk[i * CQK + ck];
                g_k16[bt * 16 + ck] = __float2bfloat16(ak);
                g_k16[bt * 16 + 8 + ck] = __float2bfloat16(0.f);
            }
        }
    }

    grid_bar(0);   // all q16/k16/v16 written

    // ================= Phase B: flash attention, 512 units over 296 groups =================
    {
        const int gidx = tid >> 7;          // group 0/1 within CTA
        const int tg   = tid & 127;         // tid within group
        const int warp = tg >> 5;
        const int lane = tg & 31;
        AttnSmem& S = smem.grp[gidx];

        for (int u = blockIdx.x * 2 + gidx; u < NUNITS; u += 2 * GRID_P) {
            const int split = u & (NSPLIT - 1);
            const int qi = (u >> 2) & 63;
            const int b  = u >> 8;
            const int q0 = qi * TQ;
            const int t_begin = split * TILES_PER_SPLIT;
            const int t_end   = t_begin + TILES_PER_SPLIT;

            const __nv_bfloat16* gk = g_k16 + (size_t)b * NTOK * 16;
            const __nv_bfloat16* gv = g_v16 + (size_t)b * NTOK * CC;

            // load Q tile (64 rows x 16)
            {
                const uint4* qsrc = (const uint4*)(g_q16 + (size_t)(b * NTOK + q0) * 16);
                const int r = tg >> 1, seg = tg & 1;
                *(uint4*)&S.Q[r * KS + seg * 8] = qsrc[tg];
            }
            group_bar(gidx);

            uint32_t qa[4];
            ldsm_x4(qa[0], qa[1], qa[2], qa[3],
                    smem_u32(&S.Q[(16 * warp + (lane & 15)) * KS + (lane >> 4) * 8]));

            float m0 = -1e30f, m1 = -1e30f;
            float l0 = 0.f, l1 = 0.f;
            float o[8][4];
#pragma unroll
            for (int ni = 0; ni < 8; ni++)
#pragma unroll
                for (int j = 0; j < 4; j++) o[ni][j] = 0.f;

            for (int t = t_begin; t < t_end; t++) {
                const int kb = t * TK;
                // load K tile
                {
                    const int r = tg >> 1, seg = tg & 1;
                    *(uint4*)&S.K[r * KS + seg * 8] =
                        *(const uint4*)(gk + (kb + r) * 16 + seg * 8);
                }
                // load V tile
#pragma unroll
                for (int j = 0; j < 4; j++) {
                    const int cchunk = tg + 128 * j;
                    const int r = cchunk >> 3, seg = cchunk & 7;
                    *(uint4*)&S.V[r * VS + seg * 8] =
                        *(const uint4*)(gv + (kb + r) * CC + seg * 8);
                }
                group_bar(gidx);

                // ---- S = Q K^T ----
                float s[8][4];
#pragma unroll
                for (int p = 0; p < 4; p++) {
                    uint32_t r0, r1, r2, r3;
                    ldsm_x4(r0, r1, r2, r3,
                            smem_u32(&S.K[(16 * p + (lane & 15)) * KS + (lane >> 4) * 8]));
                    s[2 * p][0] = s[2 * p][1] = s[2 * p][2] = s[2 * p][3] = 0.f;
                    s[2 * p + 1][0] = s[2 * p + 1][1] = s[2 * p + 1][2] = s[2 * p + 1][3] = 0.f;
                    mma_bf16(s[2 * p],     qa, r0, r2);
                    mma_bf16(s[2 * p + 1], qa, r1, r3);
                }

                // ---- online softmax (log2 domain) ----
                float mx0 = -1e30f, mx1 = -1e30f;
#pragma unroll
                for (int ni = 0; ni < 8; ni++) {
                    mx0 = fmaxf(mx0, fmaxf(s[ni][0], s[ni][1]));
                    mx1 = fmaxf(mx1, fmaxf(s[ni][2], s[ni][3]));
                }
                mx0 = fmaxf(mx0, __shfl_xor_sync(0xffffffffu, mx0, 1));
                mx0 = fmaxf(mx0, __shfl_xor_sync(0xffffffffu, mx0, 2));
                mx1 = fmaxf(mx1, __shfl_xor_sync(0xffffffffu, mx1, 1));
                mx1 = fmaxf(mx1, __shfl_xor_sync(0xffffffffu, mx1, 2));

                const float mn0 = fmaxf(m0, mx0);
                const float mn1 = fmaxf(m1, mx1);
                const float al0 = fast_ex2(m0 - mn0);
                const float al1 = fast_ex2(m1 - mn1);
                m0 = mn0; m1 = mn1;

                float ps0 = 0.f, ps1 = 0.f;
#pragma unroll
                for (int ni = 0; ni < 8; ni++) {
                    s[ni][0] = fast_ex2(s[ni][0] - mn0);
                    s[ni][1] = fast_ex2(s[ni][1] - mn0);
                    s[ni][2] = fast_ex2(s[ni][2] - mn1);
                    s[ni][3] = fast_ex2(s[ni][3] - mn1);
                    ps0 += s[ni][0] + s[ni][1];
                    ps1 += s[ni][2] + s[ni][3];
                }
                l0 = l0 * al0 + ps0;
                l1 = l1 * al1 + ps1;
#pragma unroll
                for (int ni = 0; ni < 8; ni++) {
                    o[ni][0] *= al0; o[ni][1] *= al0;
                    o[ni][2] *= al1; o[ni][3] *= al1;
                }

                // ---- P -> bf16 A-fragments ----
                uint32_t pa[4][4];
#pragma unroll
                for (int kc = 0; kc < 4; kc++) {
                    pa[kc][0] = pack_bf16x2(s[2 * kc][1],     s[2 * kc][0]);
                    pa[kc][1] = pack_bf16x2(s[2 * kc][3],     s[2 * kc][2]);
                    pa[kc][2] = pack_bf16x2(s[2 * kc + 1][1], s[2 * kc + 1][0]);
                    pa[kc][3] = pack_bf16x2(s[2 * kc + 1][3], s[2 * kc + 1][2]);
                }

                // ---- O += P V ----
#pragma unroll
                for (int kc = 0; kc < 4; kc++) {
#pragma unroll
                    for (int np = 0; np < 4; np++) {
                        uint32_t r0, r1, r2, r3;
                        ldsm_x4_t(r0, r1, r2, r3,
                                  smem_u32(&S.V[(16 * kc + (lane & 15)) * VS
                                                + np * 16 + (lane >> 4) * 8]));
                        mma_bf16(o[2 * np],     pa[kc], r0, r1);
                        mma_bf16(o[2 * np + 1], pa[kc], r2, r3);
                    }
                }
                group_bar(gidx);   // done reading tiles before next overwrite
            }

            // ---- epilogue: unnormalized partials + (m, l) ----
            l0 += __shfl_xor_sync(0xffffffffu, l0, 1);
            l0 += __shfl_xor_sync(0xffffffffu, l0, 2);
            l1 += __shfl_xor_sync(0xffffffffu, l1, 1);
            l1 += __shfl_xor_sync(0xffffffffu, l1, 2);

            const int row0 = q0 + 16 * warp + (lane >> 2);
            const int row1 = row0 + 8;
            const size_t pbase = ((size_t)split * B + b) * NTOK;
            float* out0 = g_po + (pbase + row0) * CC;
            float* out1 = g_po + (pbase + row1) * CC;
#pragma unroll
            for (int ni = 0; ni < 8; ni++) {
                const int col = 8 * ni + 2 * (lane & 3);
                *(float2*)&out0[col] = make_float2(o[ni][0], o[ni][1]);
                *(float2*)&out1[col] = make_float2(o[ni][2], o[ni][3]);
            }
            if ((lane & 3) == 0) {
                g_pm[pbase + row0] = m0;  g_pl[pbase + row0] = l0;
                g_pm[pbase + row1] = m1;  g_pl[pbase + row1] = l1;
            }
        }
    }

    grid_bar(1);   // all partials written

    // ================= Phase C: combine split partials -> g_att =================
    {
        const int c = tid & 63;
        const int rsub = tid >> 6;   // 0..3
        for (int ch = blockIdx.x; ch < 2048; ch += GRID_P) {
            const int R = ch * 4 + rsub;
            const int b = R >> 12;
            const int q = R & 4095;

            float m[NSPLIT], l[NSPLIT];
            float M = -1e30f;
#pragma unroll
            for (int s = 0; s < NSPLIT; s++) {
                const size_t idx = ((size_t)s * B + b) * NTOK + q;
                m[s] = g_pm[idx];
                l[s] = g_pl[idx];
                M = fmaxf(M, m[s]);
            }
            float L = 0.f, o = 0.f;
#pragma unroll
            for (int s = 0; s < NSPLIT; s++) {
                const float w = fast_ex2(m[s] - M);
                L += w * l[s];
                o += w * g_po[(((size_t)s * B + b) * NTOK + q) * CC + c];
            }
            g_att[((size_t)b * NTOK + q) * CC + c] = o / L;
        }
    }
}

// ---------------- fuse: out = x + gamma * upsample(attended), ILP-4 ----------------
__global__ __launch_bounds__(256) void fuse_kernel(const float* __restrict__ x,
                                                   const float* __restrict__ gamma,
                                                   float* __restrict__ out) {
    const float g = __ldg(gamma);
    const int base = blockIdx.x * 1024 + threadIdx.x;   // float4 index
    const float4* __restrict__ xv = (const float4*)x;
    float4* __restrict__ ov = (float4*)out;

    if (g == 0.0f) {
        float4 r[4];
#pragma unroll
        for (int u = 0; u < 4; u++) r[u] = __ldcs(&xv[base + 256 * u]);
#pragma unroll
        for (int u = 0; u < 4; u++) __stcs(&ov[base + 256 * u], r[u]);
        return;
    }

    float4 r[4], a[4];
#pragma unroll
    for (int u = 0; u < 4; u++) {
        const int i = base + 256 * u;
        const int c4 = i & 15;
        const int d  = (i >> 4)  & 63;
        const int w  = (i >> 10) & 63;
        const int h  = (i >> 16) & 63;
        const int b  = i >> 22;
        const int tok = ((b * NP + (h >> 2)) * NP + (w >> 2)) * NP + (d >> 2);
        r[u] = __ldcs(&xv[i]);
        a[u] = ((const float4*)g_att)[tok * 16 + c4];
    }
#pragma unroll
    for (int u = 0; u < 4; u++) {
        const int i = base + 256 * u;
        __stcs(&ov[i], make_float4(r[u].x + g * a[u].x, r[u].y + g * a[u].y,
                                   r[u].z + g * a[u].z, r[u].w + g * a[u].w));
    }
}

// ---------------- launch ----------------
extern "C" void kernel_launch(void* const* d_in, const int* in_sizes, int n_in,
                              void* d_out, int out_size) {
    const float* x     = (const float*)d_in[0];
    const float* Wq    = (const float*)d_in[1];
    const float* bq    = (const float*)d_in[2];
    const float* Wk    = (const float*)d_in[3];
    const float* bk    = (const float*)d_in[4];
    const float* Wv    = (const float*)d_in[5];
    const float* bv    = (const float*)d_in[6];
    const float* gamma = (const float*)d_in[7];
    float* out = (float*)d_out;

    prep_kernel<<<GRID_P, 256>>>(x, Wq, bq, Wk, bk, Wv, bv, gamma);
    fuse_kernel<<<TOTAL_F4 / 1024, 256>>>(x, gamma, out);   // 8192 blocks
}